// round 15
// baseline (speedup 1.0000x reference)
#include <cuda_runtime.h>
#include <cuda_bf16.h>
#include <cstdint>

// Problem constants (fixed by setup_inputs)
#define N_ROWS 8192
#define D_DIM  512
static constexpr float INV_T = 14.285714285714286f;  // 1/0.07

// Scratch (no cudaMalloc allowed)
static __device__ __nv_bfloat16 g_fnb[N_ROWS * D_DIM];   // 8 MB normalized bf16
static __device__ float g_em[N_ROWS];                    // exp(-m_i)
static __device__ float g_P[N_ROWS];
static __device__ float g_S[N_ROWS];
static __device__ float g_C[N_ROWS];
static __device__ unsigned g_done;                       // zero-init; self-resetting

// ---------------------------------------------------------------------------
// Helpers
// ---------------------------------------------------------------------------
__device__ __forceinline__ uint32_t smem_u32(const void* p) {
    uint32_t a;
    asm("{ .reg .u64 t; cvta.to.shared.u64 t, %1; cvt.u32.u64 %0, t; }" : "=r"(a) : "l"(p));
    return a;
}
__device__ __forceinline__ uint32_t sw128(uint32_t off) { return off ^ ((off >> 3) & 0x70); }

__device__ __forceinline__ void ldsm_x4(uint32_t* r, uint32_t addr) {
    asm volatile("ldmatrix.sync.aligned.m8n8.x4.shared.b16 {%0,%1,%2,%3}, [%4];"
                 : "=r"(r[0]), "=r"(r[1]), "=r"(r[2]), "=r"(r[3]) : "r"(addr));
}
__device__ __forceinline__ void mma16816(float* c, const uint32_t* a, const uint32_t* b) {
    asm volatile(
        "mma.sync.aligned.m16n8k16.row.col.f32.bf16.bf16.f32 "
        "{%0,%1,%2,%3}, {%4,%5,%6,%7}, {%8,%9}, {%0,%1,%2,%3};"
        : "+f"(c[0]), "+f"(c[1]), "+f"(c[2]), "+f"(c[3])
        : "r"(a[0]), "r"(a[1]), "r"(a[2]), "r"(a[3]), "r"(b[0]), "r"(b[1]));
}
#define CP16(dst, src) \
    asm volatile("cp.async.cg.shared.global [%0], [%1], 16;" :: "r"(dst), "l"(src))
#define CP_COMMIT()  asm volatile("cp.async.commit_group;")
#define CP_WAIT(n)   asm volatile("cp.async.wait_group %0;" :: "n"(n))

// ---------------------------------------------------------------------------
// Kernel 1: row L2-normalize, bf16 emit, em_i = exp(-||fn||^2/T), zero accums.
// ---------------------------------------------------------------------------
__global__ void normalize_kernel(const float* __restrict__ feat) {
    const int r   = blockIdx.x;
    const int tid = threadIdx.x;
    __shared__ float sbuf[4];

    const float4 f4 = reinterpret_cast<const float4*>(feat + (size_t)r * D_DIM)[tid];
    float ss = f4.x * f4.x + f4.y * f4.y + f4.z * f4.z + f4.w * f4.w;
    #pragma unroll
    for (int o = 16; o; o >>= 1) ss += __shfl_xor_sync(0xffffffffu, ss, o);
    if ((tid & 31) == 0) sbuf[tid >> 5] = ss;
    __syncthreads();
    const float tot  = sbuf[0] + sbuf[1] + sbuf[2] + sbuf[3];
    const float norm = fmaxf(sqrtf(tot), 1e-8f);

    float4 fn;
    fn.x = f4.x / norm; fn.y = f4.y / norm; fn.z = f4.z / norm; fn.w = f4.w / norm;

    float ss2 = fn.x * fn.x + fn.y * fn.y + fn.z * fn.z + fn.w * fn.w;
    #pragma unroll
    for (int o = 16; o; o >>= 1) ss2 += __shfl_xor_sync(0xffffffffu, ss2, o);
    __syncthreads();
    if ((tid & 31) == 0) sbuf[tid >> 5] = ss2;
    __syncthreads();
    const float m = (sbuf[0] + sbuf[1] + sbuf[2] + sbuf[3]) * INV_T;

    __nv_bfloat162* dst =
        reinterpret_cast<__nv_bfloat162*>(g_fnb + (size_t)r * D_DIM) + tid * 2;
    dst[0] = __floats2bfloat162_rn(fn.x, fn.y);
    dst[1] = __floats2bfloat162_rn(fn.z, fn.w);

    if (tid == 0) { g_em[r] = __expf(-m); g_P[r] = 0.f; g_S[r] = 0.f; g_C[r] = 0.f; }
}

// ---------------------------------------------------------------------------
// Kernel 2: symmetric bf16 mma.sync GEMM (clean hot loop) + per-tile
// coalesced mask pack, STAGGERED by bidx parity (odd CTAs pack before the
// K-loop, even after) so co-resident CTAs overlap pack (memory) with mma
// (tensor) + dual epilogue + fused last-CTA finalize. 2080 CTAs, occ 2.
//
// SMEM: A 3x16384 @0 | B 3x16384 @49152 | pkR @98304 (128x48) | pkC @104448 |
//       red @110592 (1024 f32) -> 114688 B
// ---------------------------------------------------------------------------
#define SM_A   0
#define SM_B   49152
#define SM_PKR 98304
#define SM_PKC 104448
#define SM_RED 110592
#define PKS    48
#define SMEM_BYTES 114688
#define K_CHUNK 64
#define N_CHUNKS (D_DIM / K_CHUNK)
#define NT 64
#define N_CTAS (NT * (NT + 1) / 2)

__global__ __launch_bounds__(256, 2)
void simloss_mma_kernel(const int* __restrict__ pos, const int* __restrict__ neg,
                        float* __restrict__ out) {
    extern __shared__ char smem[];
    __shared__ unsigned s_last;
    const uint32_t sb  = smem_u32(smem);
    const int tid    = threadIdx.x;
    const int wid    = tid >> 5;
    const int lane   = tid & 31;
    const int warp_m = wid >> 1;   // 0..3
    const int warp_n = wid & 1;    // 0..1

    // Decode upper-triangular tile (I <= J)
    const int bidx = blockIdx.x;
    int I = (int)(64.5f - sqrtf(64.5f * 64.5f - 2.0f * (float)bidx));
    while ((I + 1) * (129 - (I + 1)) / 2 <= bidx) ++I;
    while (I * (129 - I) / 2 > bidx) --I;
    const int J = I + (bidx - I * (129 - I) / 2);
    const bool diag = (I == J);
    const int i0 = I * 128;
    const int j0 = J * 128;

    float* s_rowP = reinterpret_cast<float*>(smem + SM_RED);
    float* s_rowS = s_rowP + 128;
    float* s_rowC = s_rowP + 256;
    float* s_colP = s_rowP + 384;
    float* s_colS = s_rowP + 512;
    float* s_colC = s_rowP + 640;
    float* s_emr  = s_rowP + 768;
    float* s_emc  = s_rowP + 896;

    if (tid < 128) s_emr[tid] = g_em[i0 + tid];
    else           s_emc[tid - 128] = g_em[j0 + tid - 128];
    s_rowP[tid] = 0.f; s_rowP[tid + 256] = 0.f; s_rowP[tid + 512] = 0.f;

    float acc[2][8][4];
    #pragma unroll
    for (int m = 0; m < 2; m++)
        #pragma unroll
        for (int n = 0; n < 8; n++)
            #pragma unroll
            for (int k = 0; k < 4; k++) acc[m][n][k] = 0.f;

    const int st_r = tid >> 3;
    const int st_q = tid & 7;
    auto stage = [&](int c) {
        const int b  = c % 3;
        const int kc = c * K_CHUNK;
        const __nv_bfloat16* gA = g_fnb + (size_t)i0 * D_DIM + kc;
        const __nv_bfloat16* gB = g_fnb + (size_t)j0 * D_DIM + kc;
        const uint32_t ab = sb + SM_A + b * 16384;
        const uint32_t bb = sb + SM_B + b * 16384;
        #pragma unroll
        for (int it = 0; it < 4; ++it) {
            const int r = st_r + it * 32;
            const uint32_t so = sw128(r * 128 + st_q * 16);
            CP16(ab + so, gA + (size_t)r * D_DIM + st_q * 8);
            if (!diag) CP16(bb + so, gB + (size_t)r * D_DIM + st_q * 8);
        }
        CP_COMMIT();
    };

    unsigned char* pkR = reinterpret_cast<unsigned char*>(smem) + SM_PKR;
    unsigned char* pkC = reinterpret_cast<unsigned char*>(smem) + SM_PKC;

    // Coalesced warp-per-row mask pack (R14-proven addressing).
    auto do_pack = [&]() {
        const int pr0 = wid * 16;
        const int lj  = lane * 4;
        #pragma unroll
        for (int side = 0; side < 2; ++side) {
            if (side == 1 && diag) break;
            const int rbase = side ? j0 : i0;
            const int cbase = side ? i0 : j0;
            unsigned char* pk = side ? pkC : pkR;
            #pragma unroll 2
            for (int rr = 0; rr < 16; rr += 2) {
                const int r0_ = pr0 + rr;
                const int r1_ = r0_ + 1;
                const size_t b0 = (size_t)(rbase + r0_) * N_ROWS + cbase + lj;
                const size_t b1 = (size_t)(rbase + r1_) * N_ROWS + cbase + lj;
                const int4 p0 = *reinterpret_cast<const int4*>(pos + b0);
                const int4 q0 = *reinterpret_cast<const int4*>(neg + b0);
                const int4 p1 = *reinterpret_cast<const int4*>(pos + b1);
                const int4 q1 = *reinterpret_cast<const int4*>(neg + b1);
                const int gi0 = rbase + r0_, gi1 = rbase + r1_;
                const int jc  = cbase + lj;
                unsigned v0 = 0, v1 = 0;
                v0 |= (gi0 != jc    ) ? ((p0.x ? 1u : 0u) | (q0.x ? 2u : 0u)) << 0 : 0u;
                v0 |= (gi0 != jc + 1) ? ((p0.y ? 1u : 0u) | (q0.y ? 2u : 0u)) << 2 : 0u;
                v0 |= (gi0 != jc + 2) ? ((p0.z ? 1u : 0u) | (q0.z ? 2u : 0u)) << 4 : 0u;
                v0 |= (gi0 != jc + 3) ? ((p0.w ? 1u : 0u) | (q0.w ? 2u : 0u)) << 6 : 0u;
                v1 |= (gi1 != jc    ) ? ((p1.x ? 1u : 0u) | (q1.x ? 2u : 0u)) << 0 : 0u;
                v1 |= (gi1 != jc + 1) ? ((p1.y ? 1u : 0u) | (q1.y ? 2u : 0u)) << 2 : 0u;
                v1 |= (gi1 != jc + 2) ? ((p1.z ? 1u : 0u) | (q1.z ? 2u : 0u)) << 4 : 0u;
                v1 |= (gi1 != jc + 3) ? ((p1.w ? 1u : 0u) | (q1.w ? 2u : 0u)) << 6 : 0u;
                pk[r0_ * PKS + lane] = (unsigned char)v0;
                pk[r1_ * PKS + lane] = (unsigned char)v1;
            }
        }
    };

    stage(0);
    stage(1);

    // Phase stagger: odd CTAs pack first (cp.async prologue proceeds async).
    const bool pack_first = (bidx & 1);
    if (pack_first) do_pack();

    const int a_row8 = (lane & 7) + ((lane >> 3) & 1) * 8;
    const int a_kb16 = (lane >> 4) * 16;
    const int b_row8 = ((lane >> 4) & 1) * 8 + (lane & 7);
    const int b_kb16 = ((lane >> 3) & 1) * 16;

    // -------- CLEAN GEMM hot loop (no mask work) --------
    for (int c = 0; c < N_CHUNKS; ++c) {
        if (c + 2 < N_CHUNKS) CP_WAIT(1); else CP_WAIT(0);
        __syncthreads();
        if (c + 2 < N_CHUNKS) stage(c + 2);

        const int b = c % 3;
        const uint32_t ab = sb + SM_A + b * 16384;
        const uint32_t bb = diag ? ab : (sb + SM_B + b * 16384);
        #pragma unroll
        for (int kk = 0; kk < K_CHUNK; kk += 16) {
            uint32_t afr[2][4];
            #pragma unroll
            for (int tm = 0; tm < 2; ++tm) {
                const int row = warp_m * 32 + tm * 16 + a_row8;
                ldsm_x4(afr[tm], ab + sw128(row * 128 + kk * 2 + a_kb16));
            }
            uint32_t bfr[4][4];
            #pragma unroll
            for (int tb = 0; tb < 4; ++tb) {
                const int nr = warp_n * 64 + tb * 16 + b_row8;
                ldsm_x4(bfr[tb], bb + sw128(nr * 128 + kk * 2 + b_kb16));
            }
            #pragma unroll
            for (int tm = 0; tm < 2; ++tm)
                #pragma unroll
                for (int tn = 0; tn < 8; ++tn)
                    mma16816(acc[tm][tn], afr[tm], &bfr[tn >> 1][(tn & 1) * 2]);
        }
    }

    if (!pack_first) do_pack();
    __syncthreads();   // pk tiles complete, all warps done

    // ---- Dual epilogue ----
    const int r0b = warp_m * 32 + (lane >> 2);
    const float em0a = s_emr[r0b];
    const float em1a = s_emr[r0b + 8];
    const float em0b = s_emr[r0b + 16];
    const float em1b = s_emr[r0b + 24];
    const int shR = (lane & 1) * 4;

    float rP[2][2] = {{0,0},{0,0}}, rS[2][2] = {{0,0},{0,0}}, rC[2][2] = {{0,0},{0,0}};

    #pragma unroll
    for (int tn = 0; tn < 8; ++tn) {
        const int cb = warp_n * 64 + tn * 8 + (lane & 3) * 2;
        const int cbyte = cb >> 2;
        const float emc0 = s_emc[cb], emc1 = s_emc[cb + 1];
        float cP0 = 0.f, cS0 = 0.f, cC0 = 0.f, cP1 = 0.f, cS1 = 0.f, cC1 = 0.f;
        #pragma unroll
        for (int tm = 0; tm < 2; ++tm) {
            const int r0 = r0b + tm * 16;
            const int r1 = r0 + 8;
            const float em0 = tm ? em0b : em0a;
            const float em1 = tm ? em1b : em1a;
            const float E00 = __expf(acc[tm][tn][0] * INV_T);
            const float E01 = __expf(acc[tm][tn][1] * INV_T);
            const float E10 = __expf(acc[tm][tn][2] * INV_T);
            const float E11 = __expf(acc[tm][tn][3] * INV_T);

            {   // Row side
                const unsigned v0 = (unsigned)pkR[r0 * PKS + cbyte] >> shR;
                const unsigned v1 = (unsigned)pkR[r1 * PKS + cbyte] >> shR;
                const float e00 = E00 * em0, e01 = E01 * em0;
                const float e10 = E10 * em1, e11 = E11 * em1;
                if (v0 & 1) { rP[tm][0] += e00; rC[tm][0] += 1.f; }
                if (v0 & 2) { rS[tm][0] += e00; }
                if (v0 & 4) { rP[tm][0] += e01; rC[tm][0] += 1.f; }
                if (v0 & 8) { rS[tm][0] += e01; }
                if (v1 & 1) { rP[tm][1] += e10; rC[tm][1] += 1.f; }
                if (v1 & 2) { rS[tm][1] += e10; }
                if (v1 & 4) { rP[tm][1] += e11; rC[tm][1] += 1.f; }
                if (v1 & 8) { rS[tm][1] += e11; }
            }
            if (!diag) {   // Col side
                const int rbyte0 = r0 >> 2, sh0 = (r0 & 3) * 2;
                const int rbyte1 = r1 >> 2, sh1 = (r1 & 3) * 2;
                const unsigned w00 = (unsigned)pkC[cb * PKS + rbyte0] >> sh0;
                const unsigned w10 = (unsigned)pkC[cb * PKS + rbyte1] >> sh1;
                const unsigned w01 = (unsigned)pkC[(cb + 1) * PKS + rbyte0] >> sh0;
                const unsigned w11 = (unsigned)pkC[(cb + 1) * PKS + rbyte1] >> sh1;
                const float f00 = E00 * emc0, f10 = E10 * emc0;
                const float f01 = E01 * emc1, f11 = E11 * emc1;
                if (w00 & 1) { cP0 += f00; cC0 += 1.f; }
                if (w00 & 2) { cS0 += f00; }
                if (w10 & 1) { cP0 += f10; cC0 += 1.f; }
                if (w10 & 2) { cS0 += f10; }
                if (w01 & 1) { cP1 += f01; cC1 += 1.f; }
                if (w01 & 2) { cS1 += f01; }
                if (w11 & 1) { cP1 += f11; cC1 += 1.f; }
                if (w11 & 2) { cS1 += f11; }
            }
        }
        if (!diag) {
            #pragma unroll
            for (int o = 4; o < 32; o <<= 1) {
                cP0 += __shfl_xor_sync(0xffffffffu, cP0, o);
                cS0 += __shfl_xor_sync(0xffffffffu, cS0, o);
                cC0 += __shfl_xor_sync(0xffffffffu, cC0, o);
                cP1 += __shfl_xor_sync(0xffffffffu, cP1, o);
                cS1 += __shfl_xor_sync(0xffffffffu, cS1, o);
                cC1 += __shfl_xor_sync(0xffffffffu, cC1, o);
            }
            if (lane < 4) {
                atomicAdd(&s_colP[cb], cP0); atomicAdd(&s_colP[cb + 1], cP1);
                atomicAdd(&s_colS[cb], cS0); atomicAdd(&s_colS[cb + 1], cS1);
                atomicAdd(&s_colC[cb], cC0); atomicAdd(&s_colC[cb + 1], cC1);
            }
        }
    }
    #pragma unroll
    for (int tm = 0; tm < 2; ++tm) {
        #pragma unroll
        for (int o = 1; o < 4; o <<= 1) {
            rP[tm][0] += __shfl_xor_sync(0xffffffffu, rP[tm][0], o);
            rS[tm][0] += __shfl_xor_sync(0xffffffffu, rS[tm][0], o);
            rC[tm][0] += __shfl_xor_sync(0xffffffffu, rC[tm][0], o);
            rP[tm][1] += __shfl_xor_sync(0xffffffffu, rP[tm][1], o);
            rS[tm][1] += __shfl_xor_sync(0xffffffffu, rS[tm][1], o);
            rC[tm][1] += __shfl_xor_sync(0xffffffffu, rC[tm][1], o);
        }
        if ((lane & 3) == 0) {
            const int r0 = r0b + tm * 16;
            atomicAdd(&s_rowP[r0], rP[tm][0]); atomicAdd(&s_rowP[r0 + 8], rP[tm][1]);
            atomicAdd(&s_rowS[r0], rS[tm][0]); atomicAdd(&s_rowS[r0 + 8], rS[tm][1]);
            atomicAdd(&s_rowC[r0], rC[tm][0]); atomicAdd(&s_rowC[r0 + 8], rC[tm][1]);
        }
    }
    __syncthreads();

    if (tid < 128) {
        atomicAdd(&g_P[i0 + tid], s_rowP[tid]);
        atomicAdd(&g_S[i0 + tid], s_rowS[tid]);
        atomicAdd(&g_C[i0 + tid], s_rowC[tid]);
    } else if (!diag) {
        const int c2 = tid - 128;
        atomicAdd(&g_P[j0 + c2], s_colP[c2]);
        atomicAdd(&g_S[j0 + c2], s_colS[c2]);
        atomicAdd(&g_C[j0 + c2], s_colC[c2]);
    }

    // ---- Fused finalize: last CTA reduces g_P/S/C and writes out ----
    __syncthreads();
    if (tid == 0) {
        __threadfence();
        s_last = (atomicAdd(&g_done, 1u) == (unsigned)(N_CTAS - 1)) ? 1u : 0u;
    }
    __syncthreads();
    if (s_last) {
        float local = 0.f;
        for (int i = tid; i < N_ROWS; i += 256) {
            const float C = __ldcg(&g_C[i]);
            const float P = __ldcg(&g_P[i]);
            const float S = __ldcg(&g_S[i]);
            const float L = logf(S);
            const float card = (C == 0.f) ? 1.f : C;
            local += -(P - C * L) / card;
        }
        #pragma unroll
        for (int o = 16; o; o >>= 1) local += __shfl_xor_sync(0xffffffffu, local, o);
        float* s_red = reinterpret_cast<float*>(smem + SM_RED);
        if ((lane == 0)) s_red[wid] = local;
        __syncthreads();
        if (tid < 8) {
            float v = s_red[tid];
            #pragma unroll
            for (int o = 4; o; o >>= 1) v += __shfl_xor_sync(0x000000ffu, v, o);
            if (tid == 0) { out[0] = v * (1.0f / (float)N_ROWS); g_done = 0u; }
        }
    }
}

// ---------------------------------------------------------------------------
extern "C" void kernel_launch(void* const* d_in, const int* in_sizes, int n_in,
                              void* d_out, int out_size) {
    const float* feat = (const float*)d_in[0];
    const int*   pos  = (const int*)d_in[1];
    const int*   neg  = (const int*)d_in[2];
    float*       out  = (float*)d_out;

    cudaFuncSetAttribute(simloss_mma_kernel,
                         cudaFuncAttributeMaxDynamicSharedMemorySize, SMEM_BYTES);

    normalize_kernel<<<N_ROWS, 128>>>(feat);
    simloss_mma_kernel<<<N_CTAS, 256, SMEM_BYTES>>>(pos, neg, out);
}

// round 16
// speedup vs baseline: 1.0190x; 1.0190x over previous
#include <cuda_runtime.h>
#include <cuda_bf16.h>
#include <cstdint>

// Problem constants (fixed by setup_inputs)
#define N_ROWS 8192
#define D_DIM  512
static constexpr float INV_T = 14.285714285714286f;  // 1/0.07

// Scratch (no cudaMalloc allowed)
static __device__ __nv_bfloat16 g_fnb[N_ROWS * D_DIM];   // 8 MB normalized bf16
static __device__ float g_em[N_ROWS];                    // exp(-m_i)
static __device__ float g_P[N_ROWS];
static __device__ float g_S[N_ROWS];
static __device__ float g_C[N_ROWS];
static __device__ unsigned g_done;                       // zero-init; self-resetting

// ---------------------------------------------------------------------------
// Helpers
// ---------------------------------------------------------------------------
__device__ __forceinline__ uint32_t smem_u32(const void* p) {
    uint32_t a;
    asm("{ .reg .u64 t; cvta.to.shared.u64 t, %1; cvt.u32.u64 %0, t; }" : "=r"(a) : "l"(p));
    return a;
}
__device__ __forceinline__ uint32_t sw128(uint32_t off) { return off ^ ((off >> 3) & 0x70); }

__device__ __forceinline__ void ldsm_x4(uint32_t* r, uint32_t addr) {
    asm volatile("ldmatrix.sync.aligned.m8n8.x4.shared.b16 {%0,%1,%2,%3}, [%4];"
                 : "=r"(r[0]), "=r"(r[1]), "=r"(r[2]), "=r"(r[3]) : "r"(addr));
}
__device__ __forceinline__ void mma16816(float* c, const uint32_t* a, const uint32_t* b) {
    asm volatile(
        "mma.sync.aligned.m16n8k16.row.col.f32.bf16.bf16.f32 "
        "{%0,%1,%2,%3}, {%4,%5,%6,%7}, {%8,%9}, {%0,%1,%2,%3};"
        : "+f"(c[0]), "+f"(c[1]), "+f"(c[2]), "+f"(c[3])
        : "r"(a[0]), "r"(a[1]), "r"(a[2]), "r"(a[3]), "r"(b[0]), "r"(b[1]));
}
#define CP16(dst, src) \
    asm volatile("cp.async.cg.shared.global [%0], [%1], 16;" :: "r"(dst), "l"(src))
#define CP_COMMIT()  asm volatile("cp.async.commit_group;")
#define CP_WAIT(n)   asm volatile("cp.async.wait_group %0;" :: "n"(n))

// ---------------------------------------------------------------------------
// Kernel 1: row L2-normalize, bf16 emit, em_i = exp(-||fn||^2/T), zero accums.
// ---------------------------------------------------------------------------
__global__ void normalize_kernel(const float* __restrict__ feat) {
    const int r   = blockIdx.x;
    const int tid = threadIdx.x;
    __shared__ float sbuf[4];

    const float4 f4 = reinterpret_cast<const float4*>(feat + (size_t)r * D_DIM)[tid];
    float ss = f4.x * f4.x + f4.y * f4.y + f4.z * f4.z + f4.w * f4.w;
    #pragma unroll
    for (int o = 16; o; o >>= 1) ss += __shfl_xor_sync(0xffffffffu, ss, o);
    if ((tid & 31) == 0) sbuf[tid >> 5] = ss;
    __syncthreads();
    const float tot  = sbuf[0] + sbuf[1] + sbuf[2] + sbuf[3];
    const float norm = fmaxf(sqrtf(tot), 1e-8f);

    float4 fn;
    fn.x = f4.x / norm; fn.y = f4.y / norm; fn.z = f4.z / norm; fn.w = f4.w / norm;

    float ss2 = fn.x * fn.x + fn.y * fn.y + fn.z * fn.z + fn.w * fn.w;
    #pragma unroll
    for (int o = 16; o; o >>= 1) ss2 += __shfl_xor_sync(0xffffffffu, ss2, o);
    __syncthreads();
    if ((tid & 31) == 0) sbuf[tid >> 5] = ss2;
    __syncthreads();
    const float m = (sbuf[0] + sbuf[1] + sbuf[2] + sbuf[3]) * INV_T;

    __nv_bfloat162* dst =
        reinterpret_cast<__nv_bfloat162*>(g_fnb + (size_t)r * D_DIM) + tid * 2;
    dst[0] = __floats2bfloat162_rn(fn.x, fn.y);
    dst[1] = __floats2bfloat162_rn(fn.z, fn.w);

    if (tid == 0) { g_em[r] = __expf(-m); g_P[r] = 0.f; g_S[r] = 0.f; g_C[r] = 0.f; }
}

// ---------------------------------------------------------------------------
// Kernel 2: symmetric bf16 mma.sync GEMM (clean hot loop) + per-tile
// post-loop coalesced mask pack (R14 schedule: ALL CTAs pack after the
// K-loop — wave jitter provides the pack/mma overlap across resident CTAs)
// + dual epilogue + fused last-CTA finalize. 2080 CTAs, occ 2.
//
// SMEM: A 3x16384 @0 | B 3x16384 @49152 | pkR @98304 (128x48) | pkC @104448 |
//       red @110592 (1024 f32) -> 114688 B
// ---------------------------------------------------------------------------
#define SM_A   0
#define SM_B   49152
#define SM_PKR 98304
#define SM_PKC 104448
#define SM_RED 110592
#define PKS    48
#define SMEM_BYTES 114688
#define K_CHUNK 64
#define N_CHUNKS (D_DIM / K_CHUNK)
#define NT 64
#define N_CTAS (NT * (NT + 1) / 2)

__global__ __launch_bounds__(256, 2)
void simloss_mma_kernel(const int* __restrict__ pos, const int* __restrict__ neg,
                        float* __restrict__ out) {
    extern __shared__ char smem[];
    __shared__ unsigned s_last;
    const uint32_t sb  = smem_u32(smem);
    const int tid    = threadIdx.x;
    const int wid    = tid >> 5;
    const int lane   = tid & 31;
    const int warp_m = wid >> 1;   // 0..3
    const int warp_n = wid & 1;    // 0..1

    // Decode upper-triangular tile (I <= J)
    const int bidx = blockIdx.x;
    int I = (int)(64.5f - sqrtf(64.5f * 64.5f - 2.0f * (float)bidx));
    while ((I + 1) * (129 - (I + 1)) / 2 <= bidx) ++I;
    while (I * (129 - I) / 2 > bidx) --I;
    const int J = I + (bidx - I * (129 - I) / 2);
    const bool diag = (I == J);
    const int i0 = I * 128;
    const int j0 = J * 128;

    float* s_rowP = reinterpret_cast<float*>(smem + SM_RED);
    float* s_rowS = s_rowP + 128;
    float* s_rowC = s_rowP + 256;
    float* s_colP = s_rowP + 384;
    float* s_colS = s_rowP + 512;
    float* s_colC = s_rowP + 640;
    float* s_emr  = s_rowP + 768;
    float* s_emc  = s_rowP + 896;

    if (tid < 128) s_emr[tid] = g_em[i0 + tid];
    else           s_emc[tid - 128] = g_em[j0 + tid - 128];
    s_rowP[tid] = 0.f; s_rowP[tid + 256] = 0.f; s_rowP[tid + 512] = 0.f;

    float acc[2][8][4];
    #pragma unroll
    for (int m = 0; m < 2; m++)
        #pragma unroll
        for (int n = 0; n < 8; n++)
            #pragma unroll
            for (int k = 0; k < 4; k++) acc[m][n][k] = 0.f;

    const int st_r = tid >> 3;
    const int st_q = tid & 7;
    auto stage = [&](int c) {
        const int b  = c % 3;
        const int kc = c * K_CHUNK;
        const __nv_bfloat16* gA = g_fnb + (size_t)i0 * D_DIM + kc;
        const __nv_bfloat16* gB = g_fnb + (size_t)j0 * D_DIM + kc;
        const uint32_t ab = sb + SM_A + b * 16384;
        const uint32_t bb = sb + SM_B + b * 16384;
        #pragma unroll
        for (int it = 0; it < 4; ++it) {
            const int r = st_r + it * 32;
            const uint32_t so = sw128(r * 128 + st_q * 16);
            CP16(ab + so, gA + (size_t)r * D_DIM + st_q * 8);
            if (!diag) CP16(bb + so, gB + (size_t)r * D_DIM + st_q * 8);
        }
        CP_COMMIT();
    };

    unsigned char* pkR = reinterpret_cast<unsigned char*>(smem) + SM_PKR;
    unsigned char* pkC = reinterpret_cast<unsigned char*>(smem) + SM_PKC;

    stage(0);
    stage(1);

    const int a_row8 = (lane & 7) + ((lane >> 3) & 1) * 8;
    const int a_kb16 = (lane >> 4) * 16;
    const int b_row8 = ((lane >> 4) & 1) * 8 + (lane & 7);
    const int b_kb16 = ((lane >> 3) & 1) * 16;

    // -------- CLEAN GEMM hot loop (no mask work) --------
    for (int c = 0; c < N_CHUNKS; ++c) {
        if (c + 2 < N_CHUNKS) CP_WAIT(1); else CP_WAIT(0);
        __syncthreads();
        if (c + 2 < N_CHUNKS) stage(c + 2);

        const int b = c % 3;
        const uint32_t ab = sb + SM_A + b * 16384;
        const uint32_t bb = diag ? ab : (sb + SM_B + b * 16384);
        #pragma unroll
        for (int kk = 0; kk < K_CHUNK; kk += 16) {
            uint32_t afr[2][4];
            #pragma unroll
            for (int tm = 0; tm < 2; ++tm) {
                const int row = warp_m * 32 + tm * 16 + a_row8;
                ldsm_x4(afr[tm], ab + sw128(row * 128 + kk * 2 + a_kb16));
            }
            uint32_t bfr[4][4];
            #pragma unroll
            for (int tb = 0; tb < 4; ++tb) {
                const int nr = warp_n * 64 + tb * 16 + b_row8;
                ldsm_x4(bfr[tb], bb + sw128(nr * 128 + kk * 2 + b_kb16));
            }
            #pragma unroll
            for (int tm = 0; tm < 2; ++tm)
                #pragma unroll
                for (int tn = 0; tn < 8; ++tn)
                    mma16816(acc[tm][tn], afr[tm], &bfr[tn >> 1][(tn & 1) * 2]);
        }
    }

    // -------- Pack phase: COALESCED warp-per-row mask pack (R14) --------
    {
        const int pr0 = wid * 16;
        const int lj  = lane * 4;
        #pragma unroll
        for (int side = 0; side < 2; ++side) {
            if (side == 1 && diag) break;
            const int rbase = side ? j0 : i0;
            const int cbase = side ? i0 : j0;
            unsigned char* pk = side ? pkC : pkR;
            #pragma unroll 2
            for (int rr = 0; rr < 16; rr += 2) {
                const int r0_ = pr0 + rr;
                const int r1_ = r0_ + 1;
                const size_t b0 = (size_t)(rbase + r0_) * N_ROWS + cbase + lj;
                const size_t b1 = (size_t)(rbase + r1_) * N_ROWS + cbase + lj;
                const int4 p0 = *reinterpret_cast<const int4*>(pos + b0);
                const int4 q0 = *reinterpret_cast<const int4*>(neg + b0);
                const int4 p1 = *reinterpret_cast<const int4*>(pos + b1);
                const int4 q1 = *reinterpret_cast<const int4*>(neg + b1);
                const int gi0 = rbase + r0_, gi1 = rbase + r1_;
                const int jc  = cbase + lj;
                unsigned v0 = 0, v1 = 0;
                v0 |= (gi0 != jc    ) ? ((p0.x ? 1u : 0u) | (q0.x ? 2u : 0u)) << 0 : 0u;
                v0 |= (gi0 != jc + 1) ? ((p0.y ? 1u : 0u) | (q0.y ? 2u : 0u)) << 2 : 0u;
                v0 |= (gi0 != jc + 2) ? ((p0.z ? 1u : 0u) | (q0.z ? 2u : 0u)) << 4 : 0u;
                v0 |= (gi0 != jc + 3) ? ((p0.w ? 1u : 0u) | (q0.w ? 2u : 0u)) << 6 : 0u;
                v1 |= (gi1 != jc    ) ? ((p1.x ? 1u : 0u) | (q1.x ? 2u : 0u)) << 0 : 0u;
                v1 |= (gi1 != jc + 1) ? ((p1.y ? 1u : 0u) | (q1.y ? 2u : 0u)) << 2 : 0u;
                v1 |= (gi1 != jc + 2) ? ((p1.z ? 1u : 0u) | (q1.z ? 2u : 0u)) << 4 : 0u;
                v1 |= (gi1 != jc + 3) ? ((p1.w ? 1u : 0u) | (q1.w ? 2u : 0u)) << 6 : 0u;
                pk[r0_ * PKS + lane] = (unsigned char)v0;
                pk[r1_ * PKS + lane] = (unsigned char)v1;
            }
        }
    }
    __syncthreads();   // pk tiles complete, all warps done

    // ---- Dual epilogue ----
    const int r0b = warp_m * 32 + (lane >> 2);
    const float em0a = s_emr[r0b];
    const float em1a = s_emr[r0b + 8];
    const float em0b = s_emr[r0b + 16];
    const float em1b = s_emr[r0b + 24];
    const int shR = (lane & 1) * 4;

    float rP[2][2] = {{0,0},{0,0}}, rS[2][2] = {{0,0},{0,0}}, rC[2][2] = {{0,0},{0,0}};

    #pragma unroll
    for (int tn = 0; tn < 8; ++tn) {
        const int cb = warp_n * 64 + tn * 8 + (lane & 3) * 2;
        const int cbyte = cb >> 2;
        const float emc0 = s_emc[cb], emc1 = s_emc[cb + 1];
        float cP0 = 0.f, cS0 = 0.f, cC0 = 0.f, cP1 = 0.f, cS1 = 0.f, cC1 = 0.f;
        #pragma unroll
        for (int tm = 0; tm < 2; ++tm) {
            const int r0 = r0b + tm * 16;
            const int r1 = r0 + 8;
            const float em0 = tm ? em0b : em0a;
            const float em1 = tm ? em1b : em1a;
            const float E00 = __expf(acc[tm][tn][0] * INV_T);
            const float E01 = __expf(acc[tm][tn][1] * INV_T);
            const float E10 = __expf(acc[tm][tn][2] * INV_T);
            const float E11 = __expf(acc[tm][tn][3] * INV_T);

            {   // Row side
                const unsigned v0 = (unsigned)pkR[r0 * PKS + cbyte] >> shR;
                const unsigned v1 = (unsigned)pkR[r1 * PKS + cbyte] >> shR;
                const float e00 = E00 * em0, e01 = E01 * em0;
                const float e10 = E10 * em1, e11 = E11 * em1;
                if (v0 & 1) { rP[tm][0] += e00; rC[tm][0] += 1.f; }
                if (v0 & 2) { rS[tm][0] += e00; }
                if (v0 & 4) { rP[tm][0] += e01; rC[tm][0] += 1.f; }
                if (v0 & 8) { rS[tm][0] += e01; }
                if (v1 & 1) { rP[tm][1] += e10; rC[tm][1] += 1.f; }
                if (v1 & 2) { rS[tm][1] += e10; }
                if (v1 & 4) { rP[tm][1] += e11; rC[tm][1] += 1.f; }
                if (v1 & 8) { rS[tm][1] += e11; }
            }
            if (!diag) {   // Col side
                const int rbyte0 = r0 >> 2, sh0 = (r0 & 3) * 2;
                const int rbyte1 = r1 >> 2, sh1 = (r1 & 3) * 2;
                const unsigned w00 = (unsigned)pkC[cb * PKS + rbyte0] >> sh0;
                const unsigned w10 = (unsigned)pkC[cb * PKS + rbyte1] >> sh1;
                const unsigned w01 = (unsigned)pkC[(cb + 1) * PKS + rbyte0] >> sh0;
                const unsigned w11 = (unsigned)pkC[(cb + 1) * PKS + rbyte1] >> sh1;
                const float f00 = E00 * emc0, f10 = E10 * emc0;
                const float f01 = E01 * emc1, f11 = E11 * emc1;
                if (w00 & 1) { cP0 += f00; cC0 += 1.f; }
                if (w00 & 2) { cS0 += f00; }
                if (w10 & 1) { cP0 += f10; cC0 += 1.f; }
                if (w10 & 2) { cS0 += f10; }
                if (w01 & 1) { cP1 += f01; cC1 += 1.f; }
                if (w01 & 2) { cS1 += f01; }
                if (w11 & 1) { cP1 += f11; cC1 += 1.f; }
                if (w11 & 2) { cS1 += f11; }
            }
        }
        if (!diag) {
            #pragma unroll
            for (int o = 4; o < 32; o <<= 1) {
                cP0 += __shfl_xor_sync(0xffffffffu, cP0, o);
                cS0 += __shfl_xor_sync(0xffffffffu, cS0, o);
                cC0 += __shfl_xor_sync(0xffffffffu, cC0, o);
                cP1 += __shfl_xor_sync(0xffffffffu, cP1, o);
                cS1 += __shfl_xor_sync(0xffffffffu, cS1, o);
                cC1 += __shfl_xor_sync(0xffffffffu, cC1, o);
            }
            if (lane < 4) {
                atomicAdd(&s_colP[cb], cP0); atomicAdd(&s_colP[cb + 1], cP1);
                atomicAdd(&s_colS[cb], cS0); atomicAdd(&s_colS[cb + 1], cS1);
                atomicAdd(&s_colC[cb], cC0); atomicAdd(&s_colC[cb + 1], cC1);
            }
        }
    }
    #pragma unroll
    for (int tm = 0; tm < 2; ++tm) {
        #pragma unroll
        for (int o = 1; o < 4; o <<= 1) {
            rP[tm][0] += __shfl_xor_sync(0xffffffffu, rP[tm][0], o);
            rS[tm][0] += __shfl_xor_sync(0xffffffffu, rS[tm][0], o);
            rC[tm][0] += __shfl_xor_sync(0xffffffffu, rC[tm][0], o);
            rP[tm][1] += __shfl_xor_sync(0xffffffffu, rP[tm][1], o);
            rS[tm][1] += __shfl_xor_sync(0xffffffffu, rS[tm][1], o);
            rC[tm][1] += __shfl_xor_sync(0xffffffffu, rC[tm][1], o);
        }
        if ((lane & 3) == 0) {
            const int r0 = r0b + tm * 16;
            atomicAdd(&s_rowP[r0], rP[tm][0]); atomicAdd(&s_rowP[r0 + 8], rP[tm][1]);
            atomicAdd(&s_rowS[r0], rS[tm][0]); atomicAdd(&s_rowS[r0 + 8], rS[tm][1]);
            atomicAdd(&s_rowC[r0], rC[tm][0]); atomicAdd(&s_rowC[r0 + 8], rC[tm][1]);
        }
    }
    __syncthreads();

    if (tid < 128) {
        atomicAdd(&g_P[i0 + tid], s_rowP[tid]);
        atomicAdd(&g_S[i0 + tid], s_rowS[tid]);
        atomicAdd(&g_C[i0 + tid], s_rowC[tid]);
    } else if (!diag) {
        const int c2 = tid - 128;
        atomicAdd(&g_P[j0 + c2], s_colP[c2]);
        atomicAdd(&g_S[j0 + c2], s_colS[c2]);
        atomicAdd(&g_C[j0 + c2], s_colC[c2]);
    }

    // ---- Fused finalize: last CTA reduces g_P/S/C and writes out ----
    __syncthreads();
    if (tid == 0) {
        __threadfence();
        s_last = (atomicAdd(&g_done, 1u) == (unsigned)(N_CTAS - 1)) ? 1u : 0u;
    }
    __syncthreads();
    if (s_last) {
        float local = 0.f;
        for (int i = tid; i < N_ROWS; i += 256) {
            const float C = __ldcg(&g_C[i]);
            const float P = __ldcg(&g_P[i]);
            const float S = __ldcg(&g_S[i]);
            const float L = logf(S);
            const float card = (C == 0.f) ? 1.f : C;
            local += -(P - C * L) / card;
        }
        #pragma unroll
        for (int o = 16; o; o >>= 1) local += __shfl_xor_sync(0xffffffffu, local, o);
        float* s_red = reinterpret_cast<float*>(smem + SM_RED);
        if (lane == 0) s_red[wid] = local;
        __syncthreads();
        if (tid < 8) {
            float v = s_red[tid];
            #pragma unroll
            for (int o = 4; o; o >>= 1) v += __shfl_xor_sync(0x000000ffu, v, o);
            if (tid == 0) { out[0] = v * (1.0f / (float)N_ROWS); g_done = 0u; }
        }
    }
}

// ---------------------------------------------------------------------------
extern "C" void kernel_launch(void* const* d_in, const int* in_sizes, int n_in,
                              void* d_out, int out_size) {
    const float* feat = (const float*)d_in[0];
    const int*   pos  = (const int*)d_in[1];
    const int*   neg  = (const int*)d_in[2];
    float*       out  = (float*)d_out;

    cudaFuncSetAttribute(simloss_mma_kernel,
                         cudaFuncAttributeMaxDynamicSharedMemorySize, SMEM_BYTES);

    normalize_kernel<<<N_ROWS, 128>>>(feat);
    simloss_mma_kernel<<<N_CTAS, 256, SMEM_BYTES>>>(pos, neg, out);
}

// round 17
// speedup vs baseline: 1.2146x; 1.1919x over previous
#include <cuda_runtime.h>
#include <cuda_bf16.h>
#include <cstdint>

// Problem constants (fixed by setup_inputs)
#define N_ROWS 8192
#define D_DIM  512
static constexpr float INV_T = 14.285714285714286f;  // 1/0.07

// Scratch (no cudaMalloc allowed)
static __device__ __nv_bfloat16 g_fnb[N_ROWS * D_DIM];   // 8 MB normalized bf16
static __device__ float g_em[N_ROWS];                    // exp(-m_i)
static __device__ float g_P[N_ROWS];
static __device__ float g_S[N_ROWS];
static __device__ float g_C[N_ROWS];

// ---------------------------------------------------------------------------
// Helpers
// ---------------------------------------------------------------------------
__device__ __forceinline__ uint32_t smem_u32(const void* p) {
    uint32_t a;
    asm("{ .reg .u64 t; cvta.to.shared.u64 t, %1; cvt.u32.u64 %0, t; }" : "=r"(a) : "l"(p));
    return a;
}
__device__ __forceinline__ uint32_t sw128(uint32_t off) { return off ^ ((off >> 3) & 0x70); }

__device__ __forceinline__ void ldsm_x4(uint32_t* r, uint32_t addr) {
    asm volatile("ldmatrix.sync.aligned.m8n8.x4.shared.b16 {%0,%1,%2,%3}, [%4];"
                 : "=r"(r[0]), "=r"(r[1]), "=r"(r[2]), "=r"(r[3]) : "r"(addr));
}
__device__ __forceinline__ void mma16816(float* c, const uint32_t* a, const uint32_t* b) {
    asm volatile(
        "mma.sync.aligned.m16n8k16.row.col.f32.bf16.bf16.f32 "
        "{%0,%1,%2,%3}, {%4,%5,%6,%7}, {%8,%9}, {%0,%1,%2,%3};"
        : "+f"(c[0]), "+f"(c[1]), "+f"(c[2]), "+f"(c[3])
        : "r"(a[0]), "r"(a[1]), "r"(a[2]), "r"(a[3]), "r"(b[0]), "r"(b[1]));
}
#define CP16(dst, src) \
    asm volatile("cp.async.cg.shared.global [%0], [%1], 16;" :: "r"(dst), "l"(src))
#define CP_COMMIT()  asm volatile("cp.async.commit_group;")
#define CP_WAIT(n)   asm volatile("cp.async.wait_group %0;" :: "n"(n))

// ---------------------------------------------------------------------------
// Kernel 1: row L2-normalize, bf16 emit, em_i = exp(-||fn||^2/T), zero accums.
// ---------------------------------------------------------------------------
__global__ void normalize_kernel(const float* __restrict__ feat) {
    const int r   = blockIdx.x;
    const int tid = threadIdx.x;
    __shared__ float sbuf[4];

    const float4 f4 = reinterpret_cast<const float4*>(feat + (size_t)r * D_DIM)[tid];
    float ss = f4.x * f4.x + f4.y * f4.y + f4.z * f4.z + f4.w * f4.w;
    #pragma unroll
    for (int o = 16; o; o >>= 1) ss += __shfl_xor_sync(0xffffffffu, ss, o);
    if ((tid & 31) == 0) sbuf[tid >> 5] = ss;
    __syncthreads();
    const float tot  = sbuf[0] + sbuf[1] + sbuf[2] + sbuf[3];
    const float norm = fmaxf(sqrtf(tot), 1e-8f);

    float4 fn;
    fn.x = f4.x / norm; fn.y = f4.y / norm; fn.z = f4.z / norm; fn.w = f4.w / norm;

    float ss2 = fn.x * fn.x + fn.y * fn.y + fn.z * fn.z + fn.w * fn.w;
    #pragma unroll
    for (int o = 16; o; o >>= 1) ss2 += __shfl_xor_sync(0xffffffffu, ss2, o);
    __syncthreads();
    if ((tid & 31) == 0) sbuf[tid >> 5] = ss2;
    __syncthreads();
    const float m = (sbuf[0] + sbuf[1] + sbuf[2] + sbuf[3]) * INV_T;

    __nv_bfloat162* dst =
        reinterpret_cast<__nv_bfloat162*>(g_fnb + (size_t)r * D_DIM) + tid * 2;
    dst[0] = __floats2bfloat162_rn(fn.x, fn.y);
    dst[1] = __floats2bfloat162_rn(fn.z, fn.w);

    if (tid == 0) { g_em[r] = __expf(-m); g_P[r] = 0.f; g_S[r] = 0.f; g_C[r] = 0.f; }
}

// ---------------------------------------------------------------------------
// Kernel 2: symmetric bf16 mma.sync GEMM (clean hot loop) + per-tile
// post-loop coalesced mask pack + dual epilogue (R14 structure, proven
// 201 us). Tile order: 2016 off-diagonal tiles first, 64 cheap diagonal
// tiles LAST so the partial final wave consists of short CTAs.
//
// SMEM: A 3x16384 @0 | B 3x16384 @49152 | pkR @98304 (128x48) | pkC @104448 |
//       red @110592 (1024 f32) -> 114688 B
// ---------------------------------------------------------------------------
#define SM_A   0
#define SM_B   49152
#define SM_PKR 98304
#define SM_PKC 104448
#define SM_RED 110592
#define PKS    48
#define SMEM_BYTES 114688
#define K_CHUNK 64
#define N_CHUNKS (D_DIM / K_CHUNK)
#define NT 64
#define N_OFFDIAG (NT * (NT - 1) / 2)   // 2016
#define N_CTAS (N_OFFDIAG + NT)         // 2080

__global__ __launch_bounds__(256, 2)
void simloss_mma_kernel(const int* __restrict__ pos, const int* __restrict__ neg) {
    extern __shared__ char smem[];
    const uint32_t sb  = smem_u32(smem);
    const int tid    = threadIdx.x;
    const int wid    = tid >> 5;
    const int lane   = tid & 31;
    const int warp_m = wid >> 1;   // 0..3
    const int warp_n = wid & 1;    // 0..1

    // Tile decode: bidx < N_OFFDIAG -> strict upper pair (I<J); else diagonal.
    const int bidx = blockIdx.x;
    int I, J;
    bool diag;
    if (bidx < N_OFFDIAG) {
        diag = false;
        const float bf = (float)bidx;
        I = (int)(63.5f - sqrtf(63.5f * 63.5f - 2.0f * bf));
        if (I < 0) I = 0;
        if (I > 62) I = 62;
        // S(I) = I*(127-I)/2 = count of pairs with first index < I
        while (I < 62 && (I + 1) * (127 - (I + 1)) / 2 <= bidx) ++I;
        while (I > 0 && I * (127 - I) / 2 > bidx) --I;
        J = I + 1 + (bidx - I * (127 - I) / 2);
    } else {
        diag = true;
        I = J = bidx - N_OFFDIAG;
    }
    const int i0 = I * 128;
    const int j0 = J * 128;

    float* s_rowP = reinterpret_cast<float*>(smem + SM_RED);
    float* s_rowS = s_rowP + 128;
    float* s_rowC = s_rowP + 256;
    float* s_colP = s_rowP + 384;
    float* s_colS = s_rowP + 512;
    float* s_colC = s_rowP + 640;
    float* s_emr  = s_rowP + 768;
    float* s_emc  = s_rowP + 896;

    if (tid < 128) s_emr[tid] = g_em[i0 + tid];
    else           s_emc[tid - 128] = g_em[j0 + tid - 128];
    s_rowP[tid] = 0.f; s_rowP[tid + 256] = 0.f; s_rowP[tid + 512] = 0.f;

    float acc[2][8][4];
    #pragma unroll
    for (int m = 0; m < 2; m++)
        #pragma unroll
        for (int n = 0; n < 8; n++)
            #pragma unroll
            for (int k = 0; k < 4; k++) acc[m][n][k] = 0.f;

    const int st_r = tid >> 3;
    const int st_q = tid & 7;
    auto stage = [&](int c) {
        const int b  = c % 3;
        const int kc = c * K_CHUNK;
        const __nv_bfloat16* gA = g_fnb + (size_t)i0 * D_DIM + kc;
        const __nv_bfloat16* gB = g_fnb + (size_t)j0 * D_DIM + kc;
        const uint32_t ab = sb + SM_A + b * 16384;
        const uint32_t bb = sb + SM_B + b * 16384;
        #pragma unroll
        for (int it = 0; it < 4; ++it) {
            const int r = st_r + it * 32;
            const uint32_t so = sw128(r * 128 + st_q * 16);
            CP16(ab + so, gA + (size_t)r * D_DIM + st_q * 8);
            if (!diag) CP16(bb + so, gB + (size_t)r * D_DIM + st_q * 8);
        }
        CP_COMMIT();
    };

    unsigned char* pkR = reinterpret_cast<unsigned char*>(smem) + SM_PKR;
    unsigned char* pkC = reinterpret_cast<unsigned char*>(smem) + SM_PKC;

    stage(0);
    stage(1);

    const int a_row8 = (lane & 7) + ((lane >> 3) & 1) * 8;
    const int a_kb16 = (lane >> 4) * 16;
    const int b_row8 = ((lane >> 4) & 1) * 8 + (lane & 7);
    const int b_kb16 = ((lane >> 3) & 1) * 16;

    // -------- CLEAN GEMM hot loop (no mask work) --------
    for (int c = 0; c < N_CHUNKS; ++c) {
        if (c + 2 < N_CHUNKS) CP_WAIT(1); else CP_WAIT(0);
        __syncthreads();
        if (c + 2 < N_CHUNKS) stage(c + 2);

        const int b = c % 3;
        const uint32_t ab = sb + SM_A + b * 16384;
        const uint32_t bb = diag ? ab : (sb + SM_B + b * 16384);
        #pragma unroll
        for (int kk = 0; kk < K_CHUNK; kk += 16) {
            uint32_t afr[2][4];
            #pragma unroll
            for (int tm = 0; tm < 2; ++tm) {
                const int row = warp_m * 32 + tm * 16 + a_row8;
                ldsm_x4(afr[tm], ab + sw128(row * 128 + kk * 2 + a_kb16));
            }
            uint32_t bfr[4][4];
            #pragma unroll
            for (int tb = 0; tb < 4; ++tb) {
                const int nr = warp_n * 64 + tb * 16 + b_row8;
                ldsm_x4(bfr[tb], bb + sw128(nr * 128 + kk * 2 + b_kb16));
            }
            #pragma unroll
            for (int tm = 0; tm < 2; ++tm)
                #pragma unroll
                for (int tn = 0; tn < 8; ++tn)
                    mma16816(acc[tm][tn], afr[tm], &bfr[tn >> 1][(tn & 1) * 2]);
        }
    }

    // -------- Pack phase: COALESCED warp-per-row mask pack (R14) --------
    {
        const int pr0 = wid * 16;
        const int lj  = lane * 4;
        #pragma unroll
        for (int side = 0; side < 2; ++side) {
            if (side == 1 && diag) break;
            const int rbase = side ? j0 : i0;
            const int cbase = side ? i0 : j0;
            unsigned char* pk = side ? pkC : pkR;
            #pragma unroll 2
            for (int rr = 0; rr < 16; rr += 2) {
                const int r0_ = pr0 + rr;
                const int r1_ = r0_ + 1;
                const size_t b0 = (size_t)(rbase + r0_) * N_ROWS + cbase + lj;
                const size_t b1 = (size_t)(rbase + r1_) * N_ROWS + cbase + lj;
                const int4 p0 = *reinterpret_cast<const int4*>(pos + b0);
                const int4 q0 = *reinterpret_cast<const int4*>(neg + b0);
                const int4 p1 = *reinterpret_cast<const int4*>(pos + b1);
                const int4 q1 = *reinterpret_cast<const int4*>(neg + b1);
                const int gi0 = rbase + r0_, gi1 = rbase + r1_;
                const int jc  = cbase + lj;
                unsigned v0 = 0, v1 = 0;
                v0 |= (gi0 != jc    ) ? ((p0.x ? 1u : 0u) | (q0.x ? 2u : 0u)) << 0 : 0u;
                v0 |= (gi0 != jc + 1) ? ((p0.y ? 1u : 0u) | (q0.y ? 2u : 0u)) << 2 : 0u;
                v0 |= (gi0 != jc + 2) ? ((p0.z ? 1u : 0u) | (q0.z ? 2u : 0u)) << 4 : 0u;
                v0 |= (gi0 != jc + 3) ? ((p0.w ? 1u : 0u) | (q0.w ? 2u : 0u)) << 6 : 0u;
                v1 |= (gi1 != jc    ) ? ((p1.x ? 1u : 0u) | (q1.x ? 2u : 0u)) << 0 : 0u;
                v1 |= (gi1 != jc + 1) ? ((p1.y ? 1u : 0u) | (q1.y ? 2u : 0u)) << 2 : 0u;
                v1 |= (gi1 != jc + 2) ? ((p1.z ? 1u : 0u) | (q1.z ? 2u : 0u)) << 4 : 0u;
                v1 |= (gi1 != jc + 3) ? ((p1.w ? 1u : 0u) | (q1.w ? 2u : 0u)) << 6 : 0u;
                pk[r0_ * PKS + lane] = (unsigned char)v0;
                pk[r1_ * PKS + lane] = (unsigned char)v1;
            }
        }
    }
    __syncthreads();   // pk tiles complete, all warps done

    // ---- Dual epilogue ----
    const int r0b = warp_m * 32 + (lane >> 2);
    const float em0a = s_emr[r0b];
    const float em1a = s_emr[r0b + 8];
    const float em0b = s_emr[r0b + 16];
    const float em1b = s_emr[r0b + 24];
    const int shR = (lane & 1) * 4;

    float rP[2][2] = {{0,0},{0,0}}, rS[2][2] = {{0,0},{0,0}}, rC[2][2] = {{0,0},{0,0}};

    #pragma unroll
    for (int tn = 0; tn < 8; ++tn) {
        const int cb = warp_n * 64 + tn * 8 + (lane & 3) * 2;
        const int cbyte = cb >> 2;
        const float emc0 = s_emc[cb], emc1 = s_emc[cb + 1];
        float cP0 = 0.f, cS0 = 0.f, cC0 = 0.f, cP1 = 0.f, cS1 = 0.f, cC1 = 0.f;
        #pragma unroll
        for (int tm = 0; tm < 2; ++tm) {
            const int r0 = r0b + tm * 16;
            const int r1 = r0 + 8;
            const float em0 = tm ? em0b : em0a;
            const float em1 = tm ? em1b : em1a;
            const float E00 = __expf(acc[tm][tn][0] * INV_T);
            const float E01 = __expf(acc[tm][tn][1] * INV_T);
            const float E10 = __expf(acc[tm][tn][2] * INV_T);
            const float E11 = __expf(acc[tm][tn][3] * INV_T);

            {   // Row side
                const unsigned v0 = (unsigned)pkR[r0 * PKS + cbyte] >> shR;
                const unsigned v1 = (unsigned)pkR[r1 * PKS + cbyte] >> shR;
                const float e00 = E00 * em0, e01 = E01 * em0;
                const float e10 = E10 * em1, e11 = E11 * em1;
                if (v0 & 1) { rP[tm][0] += e00; rC[tm][0] += 1.f; }
                if (v0 & 2) { rS[tm][0] += e00; }
                if (v0 & 4) { rP[tm][0] += e01; rC[tm][0] += 1.f; }
                if (v0 & 8) { rS[tm][0] += e01; }
                if (v1 & 1) { rP[tm][1] += e10; rC[tm][1] += 1.f; }
                if (v1 & 2) { rS[tm][1] += e10; }
                if (v1 & 4) { rP[tm][1] += e11; rC[tm][1] += 1.f; }
                if (v1 & 8) { rS[tm][1] += e11; }
            }
            if (!diag) {   // Col side
                const int rbyte0 = r0 >> 2, sh0 = (r0 & 3) * 2;
                const int rbyte1 = r1 >> 2, sh1 = (r1 & 3) * 2;
                const unsigned w00 = (unsigned)pkC[cb * PKS + rbyte0] >> sh0;
                const unsigned w10 = (unsigned)pkC[cb * PKS + rbyte1] >> sh1;
                const unsigned w01 = (unsigned)pkC[(cb + 1) * PKS + rbyte0] >> sh0;
                const unsigned w11 = (unsigned)pkC[(cb + 1) * PKS + rbyte1] >> sh1;
                const float f00 = E00 * emc0, f10 = E10 * emc0;
                const float f01 = E01 * emc1, f11 = E11 * emc1;
                if (w00 & 1) { cP0 += f00; cC0 += 1.f; }
                if (w00 & 2) { cS0 += f00; }
                if (w10 & 1) { cP0 += f10; cC0 += 1.f; }
                if (w10 & 2) { cS0 += f10; }
                if (w01 & 1) { cP1 += f01; cC1 += 1.f; }
                if (w01 & 2) { cS1 += f01; }
                if (w11 & 1) { cP1 += f11; cC1 += 1.f; }
                if (w11 & 2) { cS1 += f11; }
            }
        }
        if (!diag) {
            #pragma unroll
            for (int o = 4; o < 32; o <<= 1) {
                cP0 += __shfl_xor_sync(0xffffffffu, cP0, o);
                cS0 += __shfl_xor_sync(0xffffffffu, cS0, o);
                cC0 += __shfl_xor_sync(0xffffffffu, cC0, o);
                cP1 += __shfl_xor_sync(0xffffffffu, cP1, o);
                cS1 += __shfl_xor_sync(0xffffffffu, cS1, o);
                cC1 += __shfl_xor_sync(0xffffffffu, cC1, o);
            }
            if (lane < 4) {
                atomicAdd(&s_colP[cb], cP0); atomicAdd(&s_colP[cb + 1], cP1);
                atomicAdd(&s_colS[cb], cS0); atomicAdd(&s_colS[cb + 1], cS1);
                atomicAdd(&s_colC[cb], cC0); atomicAdd(&s_colC[cb + 1], cC1);
            }
        }
    }
    #pragma unroll
    for (int tm = 0; tm < 2; ++tm) {
        #pragma unroll
        for (int o = 1; o < 4; o <<= 1) {
            rP[tm][0] += __shfl_xor_sync(0xffffffffu, rP[tm][0], o);
            rS[tm][0] += __shfl_xor_sync(0xffffffffu, rS[tm][0], o);
            rC[tm][0] += __shfl_xor_sync(0xffffffffu, rC[tm][0], o);
            rP[tm][1] += __shfl_xor_sync(0xffffffffu, rP[tm][1], o);
            rS[tm][1] += __shfl_xor_sync(0xffffffffu, rS[tm][1], o);
            rC[tm][1] += __shfl_xor_sync(0xffffffffu, rC[tm][1], o);
        }
        if ((lane & 3) == 0) {
            const int r0 = r0b + tm * 16;
            atomicAdd(&s_rowP[r0], rP[tm][0]); atomicAdd(&s_rowP[r0 + 8], rP[tm][1]);
            atomicAdd(&s_rowS[r0], rS[tm][0]); atomicAdd(&s_rowS[r0 + 8], rS[tm][1]);
            atomicAdd(&s_rowC[r0], rC[tm][0]); atomicAdd(&s_rowC[r0 + 8], rC[tm][1]);
        }
    }
    __syncthreads();

    if (tid < 128) {
        atomicAdd(&g_P[i0 + tid], s_rowP[tid]);
        atomicAdd(&g_S[i0 + tid], s_rowS[tid]);
        atomicAdd(&g_C[i0 + tid], s_rowC[tid]);
    } else if (!diag) {
        const int c2 = tid - 128;
        atomicAdd(&g_P[j0 + c2], s_colP[c2]);
        atomicAdd(&g_S[j0 + c2], s_colS[c2]);
        atomicAdd(&g_C[j0 + c2], s_colC[c2]);
    }
}

// ---------------------------------------------------------------------------
// Kernel 3: per-row loss + mean.
// ---------------------------------------------------------------------------
__global__ void finalize_kernel(float* __restrict__ out) {
    __shared__ float sbuf[32];
    const int tid = threadIdx.x;
    float local = 0.f;
    for (int i = tid; i < N_ROWS; i += 1024) {
        const float C = g_C[i];
        const float P = g_P[i];
        const float S = g_S[i];
        const float L = logf(S);
        const float card = (C == 0.f) ? 1.f : C;
        local += -(P - C * L) / card;
    }
    #pragma unroll
    for (int o = 16; o; o >>= 1) local += __shfl_xor_sync(0xffffffffu, local, o);
    if ((tid & 31) == 0) sbuf[tid >> 5] = local;
    __syncthreads();
    if (tid < 32) {
        float v = sbuf[tid];
        #pragma unroll
        for (int o = 16; o; o >>= 1) v += __shfl_xor_sync(0xffffffffu, v, o);
        if (tid == 0) out[0] = v * (1.0f / (float)N_ROWS);
    }
}

// ---------------------------------------------------------------------------
extern "C" void kernel_launch(void* const* d_in, const int* in_sizes, int n_in,
                              void* d_out, int out_size) {
    const float* feat = (const float*)d_in[0];
    const int*   pos  = (const int*)d_in[1];
    const int*   neg  = (const int*)d_in[2];
    float*       out  = (float*)d_out;

    cudaFuncSetAttribute(simloss_mma_kernel,
                         cudaFuncAttributeMaxDynamicSharedMemorySize, SMEM_BYTES);

    normalize_kernel<<<N_ROWS, 128>>>(feat);
    simloss_mma_kernel<<<N_CTAS, 256, SMEM_BYTES>>>(pos, neg);
    finalize_kernel<<<1, 1024>>>(out);
}